// round 3
// baseline (speedup 1.0000x reference)
#include <cuda_runtime.h>
#include <math.h>

#define N_NODES 50000
#define N_EDGES 800000
#define IN_CH 128
#define OUT_CH 32
#define HEADS 4
#define N_TYPES 4
#define N_CONF 5
#define D_OUT 128                 /* HEADS*OUT_CH */
#define SEG (N_TYPES * N_NODES)   /* 200000 (dst,type) segments */
#define MAXDEG 128                /* slots per segment (Poisson(4): overflow ~impossible) */
#define S_PAD 32                  /* padded floats per (t,n) score row (20 used) */

/* ------------------------- device scratch (static, no allocation) ---------- */
__device__ float g_xt[(size_t)N_TYPES * N_NODES * D_OUT];          /* 102.4 MB */
__device__ float g_si[(size_t)N_TYPES * N_NODES * S_PAD];          /* 25.6 MB */
__device__ float g_sj[(size_t)N_TYPES * N_NODES * S_PAD];          /* 25.6 MB */
__device__ int   g_cnt[SEG];
__device__ int   g_rec[(size_t)SEG * MAXDEG];                      /* 102.4 MB */

/* ------------------------- f32x2 packed FMA helpers ------------------------ */
__device__ __forceinline__ unsigned long long f2dup(float v) {
    unsigned long long r;
    asm("mov.b64 %0, {%1, %1};" : "=l"(r) : "f"(v));
    return r;
}
__device__ __forceinline__ unsigned long long f2pack(float x, float y) {
    unsigned long long r;
    asm("mov.b64 %0, {%1, %2};" : "=l"(r) : "f"(x), "f"(y));
    return r;
}
__device__ __forceinline__ void ffma2(unsigned long long& c, unsigned long long a,
                                      unsigned long long b) {
    asm("fma.rn.f32x2 %0, %1, %2, %0;" : "+l"(c) : "l"(a), "l"(b));
}
__device__ __forceinline__ float2 f2unpack(unsigned long long v) {
    float2 r;
    asm("mov.b64 {%0, %1}, %2;" : "=f"(r.x), "=f"(r.y) : "l"(v));
    return r;
}

/* ============================================================================
 * K1: xt[t] = x @ W[t]  (M=50000, K=128, N=128) x 4 types, fp32 via f32x2.
 * ==========================================================================*/
__global__ __launch_bounds__(256) void gemm_kernel(const float* __restrict__ x,
                                                   const float* __restrict__ W) {
    __shared__ float As[32][132];
    __shared__ float Bs[32][128];

    const int t   = blockIdx.y;
    const int n0  = blockIdx.x * 128;
    const int tid = threadIdx.x;
    const int tx  = tid & 15, ty = tid >> 4;
    const float* Wt = W + (size_t)t * IN_CH * D_OUT;

    unsigned long long acc[8][4];
#pragma unroll
    for (int i = 0; i < 8; i++)
#pragma unroll
        for (int j = 0; j < 4; j++) acc[i][j] = 0ULL;

    for (int kc = 0; kc < 4; kc++) {
#pragma unroll
        for (int it = 0; it < 4; it++) {
            int f = tid + it * 256;
            int r = f >> 3, c4 = f & 7;
            int n = n0 + r;
            float4 v = make_float4(0.f, 0.f, 0.f, 0.f);
            if (n < N_NODES)
                v = *(const float4*)(x + (size_t)n * IN_CH + kc * 32 + c4 * 4);
            As[c4 * 4 + 0][r] = v.x;
            As[c4 * 4 + 1][r] = v.y;
            As[c4 * 4 + 2][r] = v.z;
            As[c4 * 4 + 3][r] = v.w;
        }
#pragma unroll
        for (int it = 0; it < 4; it++) {
            int f = tid + it * 256;
            int kk = f >> 5, n4 = f & 31;
            float4 v = *(const float4*)(Wt + (size_t)(kc * 32 + kk) * D_OUT + n4 * 4);
            *(float4*)(&Bs[kk][n4 * 4]) = v;
        }
        __syncthreads();
#pragma unroll
        for (int kk = 0; kk < 32; kk++) {
            float4 a0 = *(const float4*)(&As[kk][ty * 8]);
            float4 a1 = *(const float4*)(&As[kk][ty * 8 + 4]);
            float4 b0 = *(const float4*)(&Bs[kk][tx * 8]);
            float4 b1 = *(const float4*)(&Bs[kk][tx * 8 + 4]);
            unsigned long long bp0 = f2pack(b0.x, b0.y);
            unsigned long long bp1 = f2pack(b0.z, b0.w);
            unsigned long long bp2 = f2pack(b1.x, b1.y);
            unsigned long long bp3 = f2pack(b1.z, b1.w);
            float av[8] = {a0.x, a0.y, a0.z, a0.w, a1.x, a1.y, a1.z, a1.w};
#pragma unroll
            for (int i = 0; i < 8; i++) {
                unsigned long long ad = f2dup(av[i]);
                ffma2(acc[i][0], ad, bp0);
                ffma2(acc[i][1], ad, bp1);
                ffma2(acc[i][2], ad, bp2);
                ffma2(acc[i][3], ad, bp3);
            }
        }
        __syncthreads();
    }
#pragma unroll
    for (int i = 0; i < 8; i++) {
        int n = n0 + ty * 8 + i;
        if (n >= N_NODES) break;
        float* dst = g_xt + ((size_t)t * N_NODES + n) * D_OUT + tx * 8;
        float2 p0 = f2unpack(acc[i][0]), p1 = f2unpack(acc[i][1]);
        float2 p2 = f2unpack(acc[i][2]), p3 = f2unpack(acc[i][3]);
        *(float4*)dst       = make_float4(p0.x, p0.y, p1.x, p1.y);
        *(float4*)(dst + 4) = make_float4(p2.x, p2.y, p3.x, p3.y);
    }
}

/* ============================================================================
 * K2: per-(type,node,head) endpoint scores, padded row stride S_PAD
 * ==========================================================================*/
__global__ __launch_bounds__(256) void score_kernel(const float* __restrict__ att) {
    __shared__ float att_s[N_CONF * HEADS * 2 * OUT_CH]; /* 1280 floats */
    for (int i = threadIdx.x; i < N_CONF * HEADS * 2 * OUT_CH; i += 256)
        att_s[i] = att[i];
    __syncthreads();

    int id = blockIdx.x * 256 + threadIdx.x;
    if (id >= SEG * HEADS) return;
    int h  = id & 3;
    int nn = id >> 2;   /* = t*N + n */

    const float4* v4 = (const float4*)(g_xt + (size_t)nn * D_OUT + h * 32);
    float si[5] = {0, 0, 0, 0, 0}, sj[5] = {0, 0, 0, 0, 0};
#pragma unroll
    for (int q = 0; q < 8; q++) {
        float4 v = v4[q];
#pragma unroll
        for (int k = 0; k < N_CONF; k++) {
            float4 ai = ((const float4*)att_s)[(k * HEADS + h) * 16 + q];
            float4 aj = ((const float4*)att_s)[(k * HEADS + h) * 16 + 8 + q];
            si[k] += v.x * ai.x + v.y * ai.y + v.z * ai.z + v.w * ai.w;
            sj[k] += v.x * aj.x + v.y * aj.y + v.z * aj.z + v.w * aj.w;
        }
    }
    float* so_i = g_si + (size_t)nn * S_PAD + h * N_CONF;
    float* so_j = g_sj + (size_t)nn * S_PAD + h * N_CONF;
#pragma unroll
    for (int k = 0; k < N_CONF; k++) { so_i[k] = si[k]; so_j[k] = sj[k]; }
}

/* ============================================================================
 * K3: direct slotted bucket build (replaces hist+scan+scatter)
 * ==========================================================================*/
__global__ void build_kernel(const int* __restrict__ ei, const int* __restrict__ et) {
    int e = blockIdx.x * 256 + threadIdx.x;
    if (e >= N_EDGES) return;
    int src = ei[e];
    int d   = ei[N_EDGES + e];
    int t   = et[e];
    int seg = d * 4 + t;
    int pos = atomicAdd(&g_cnt[seg], 1);
    if (pos < MAXDEG) g_rec[((size_t)seg << 7) + pos] = src;
}

/* ============================================================================
 * K4: one warp per dst node; flattened edge-parallel softmax, register alpha.
 * ==========================================================================*/
__device__ __forceinline__ float sel4(const float* a, int t) {
    return t == 0 ? a[0] : t == 1 ? a[1] : t == 2 ? a[2] : a[3];
}

__global__ __launch_bounds__(256) void node_kernel(const float* __restrict__ conf,
                                                   const float* __restrict__ eimp,
                                                   const float* __restrict__ bias,
                                                   float* __restrict__ out) {
    const unsigned FULL = 0xffffffffu;
    int gw   = (blockIdx.x * blockDim.x + threadIdx.x) >> 5;
    int lane = threadIdx.x & 31;
    if (gw >= N_NODES) return;
    const int dst = gw;
    const int hl  = lane >> 3;   /* head for this lane's channels */

    /* pk = softmax(confounder_probs) */
    float c0 = conf[0], c1 = conf[1], c2 = conf[2], c3 = conf[3], c4 = conf[4];
    float mx = fmaxf(fmaxf(fmaxf(c0, c1), fmaxf(c2, c3)), c4);
    float e0 = __expf(c0 - mx), e1 = __expf(c1 - mx), e2 = __expf(c2 - mx);
    float e3 = __expf(c3 - mx), e4 = __expf(c4 - mx);
    float inv = 1.f / (e0 + e1 + e2 + e3 + e4);
    float pk[5] = {e0 * inv, e1 * inv, e2 * inv, e3 * inv, e4 * inv};
    float eim[4] = {eimp[0], eimp[1], eimp[2], eimp[3]};

    /* segment counts, flattened prefix over types */
    int4 cv = *(const int4*)(g_cnt + dst * 4);
    int cc0 = min(cv.x, MAXDEG), cc1 = min(cv.y, MAXDEG);
    int cc2 = min(cv.z, MAXDEG), cc3 = min(cv.w, MAXDEG);
    int p1 = cc0, p2 = p1 + cc1, p3 = p2 + cc2;
    int total = p3 + cc3;

    /* ---- chunk0: one edge per lane (covers total<=32, i.e. ~all nodes) ---- */
    int e = lane;
    bool act = e < total;
    int myt  = (e < p1) ? 0 : (e < p2) ? 1 : (e < p3) ? 2 : 3;
    int base = (e < p1) ? 0 : (e < p2) ? p1 : (e < p3) ? p2 : p3;
    int src  = 0;
    if (act) src = g_rec[(((size_t)dst * 4 + myt) << 7) + (e - base)];

    float a0[4] = {0.f, 0.f, 0.f, 0.f};
    {
        int tt = act ? myt : 0;
        int ss = act ? src : 0;
        const float4* sip = (const float4*)(g_si + ((size_t)tt * N_NODES + dst) * S_PAD);
        const float4* sjp = (const float4*)(g_sj + ((size_t)tt * N_NODES + ss) * S_PAD);
        float si[20], sj[20];
#pragma unroll
        for (int q = 0; q < 5; q++) {
            float4 u = sip[q];
            si[q * 4 + 0] = u.x; si[q * 4 + 1] = u.y; si[q * 4 + 2] = u.z; si[q * 4 + 3] = u.w;
            float4 v = sjp[q];
            sj[q * 4 + 0] = v.x; sj[q * 4 + 1] = v.y; sj[q * 4 + 2] = v.z; sj[q * 4 + 3] = v.w;
        }
#pragma unroll
        for (int h = 0; h < 4; h++) {
            float ah = 0.f;
#pragma unroll
            for (int k = 0; k < N_CONF; k++) {
                float v = si[h * 5 + k] + sj[h * 5 + k];
                v = (v > 0.f) ? v : 0.2f * v;
                ah += pk[k] * v;
            }
            a0[h] = ah;
        }
    }

    /* ---- per-(type,head) max across warp ---- */
    float m_arr[16];
#pragma unroll
    for (int tt = 0; tt < 4; tt++)
#pragma unroll
        for (int hh = 0; hh < 4; hh++) {
            float v = (act && myt == tt) ? a0[hh] : -1e30f;
#pragma unroll
            for (int o = 16; o; o >>= 1) v = fmaxf(v, __shfl_xor_sync(FULL, v, o));
            m_arr[tt * 4 + hh] = v;
        }

    /* rare extras (total > 32): recompute alphas for max */
#pragma unroll 1
    for (int eb = 32; eb < total; eb += 32) {
        int e2 = eb + lane;
        bool a2 = e2 < total;
        int t2 = (e2 < p1) ? 0 : (e2 < p2) ? 1 : (e2 < p3) ? 2 : 3;
        int b2 = (e2 < p1) ? 0 : (e2 < p2) ? p1 : (e2 < p3) ? p2 : p3;
        int s2 = 0;
        if (a2) s2 = g_rec[(((size_t)dst * 4 + t2) << 7) + (e2 - b2)];
        int ttc = a2 ? t2 : 0;
        const float* sirow = g_si + ((size_t)ttc * N_NODES + dst) * S_PAD;
        const float* sjrow = g_sj + ((size_t)ttc * N_NODES + (a2 ? s2 : 0)) * S_PAD;
        float aa[4];
#pragma unroll
        for (int h = 0; h < 4; h++) {
            float ah = 0.f;
#pragma unroll
            for (int k = 0; k < N_CONF; k++) {
                float v = sirow[h * 5 + k] + sjrow[h * 5 + k];
                v = (v > 0.f) ? v : 0.2f * v;
                ah += pk[k] * v;
            }
            aa[h] = ah;
        }
#pragma unroll
        for (int tt = 0; tt < 4; tt++)
#pragma unroll
            for (int hh = 0; hh < 4; hh++) {
                float v = (a2 && t2 == tt) ? aa[hh] : -1e30f;
#pragma unroll
                for (int o = 16; o; o >>= 1) v = fmaxf(v, __shfl_xor_sync(FULL, v, o));
                m_arr[tt * 4 + hh] = fmaxf(m_arr[tt * 4 + hh], v);
            }
    }

    /* ---- per-(type,head) exp-sum ---- */
    float d_arr[16];
#pragma unroll
    for (int tt = 0; tt < 4; tt++)
#pragma unroll
        for (int hh = 0; hh < 4; hh++) {
            float v = (act && myt == tt) ? __expf(a0[hh] - m_arr[tt * 4 + hh]) : 0.f;
#pragma unroll
            for (int o = 16; o; o >>= 1) v += __shfl_xor_sync(FULL, v, o);
            d_arr[tt * 4 + hh] = v;
        }
#pragma unroll 1
    for (int eb = 32; eb < total; eb += 32) {
        int e2 = eb + lane;
        bool a2 = e2 < total;
        int t2 = (e2 < p1) ? 0 : (e2 < p2) ? 1 : (e2 < p3) ? 2 : 3;
        int b2 = (e2 < p1) ? 0 : (e2 < p2) ? p1 : (e2 < p3) ? p2 : p3;
        int s2 = 0;
        if (a2) s2 = g_rec[(((size_t)dst * 4 + t2) << 7) + (e2 - b2)];
        int ttc = a2 ? t2 : 0;
        const float* sirow = g_si + ((size_t)ttc * N_NODES + dst) * S_PAD;
        const float* sjrow = g_sj + ((size_t)ttc * N_NODES + (a2 ? s2 : 0)) * S_PAD;
        float aa[4];
#pragma unroll
        for (int h = 0; h < 4; h++) {
            float ah = 0.f;
#pragma unroll
            for (int k = 0; k < N_CONF; k++) {
                float v = sirow[h * 5 + k] + sjrow[h * 5 + k];
                v = (v > 0.f) ? v : 0.2f * v;
                ah += pk[k] * v;
            }
            aa[h] = ah;
        }
#pragma unroll
        for (int tt = 0; tt < 4; tt++)
#pragma unroll
            for (int hh = 0; hh < 4; hh++) {
                float v = (a2 && t2 == tt) ? __expf(aa[hh] - m_arr[tt * 4 + hh]) : 0.f;
#pragma unroll
                for (int o = 16; o; o >>= 1) v += __shfl_xor_sync(FULL, v, o);
                d_arr[tt * 4 + hh] += v;
            }
    }

    /* ---- per-lane normalized weights (chunk0 edges) ---- */
    float w[4];
    {
        float mh[4], dh[4];
#pragma unroll
        for (int h = 0; h < 4; h++) {
            mh[h] = myt == 0 ? m_arr[h] : myt == 1 ? m_arr[4 + h]
                  : myt == 2 ? m_arr[8 + h] : m_arr[12 + h];
            dh[h] = myt == 0 ? d_arr[h] : myt == 1 ? d_arr[4 + h]
                  : myt == 2 ? d_arr[8 + h] : d_arr[12 + h];
        }
        float es = sel4(eim, myt);
#pragma unroll
        for (int h = 0; h < 4; h++)
            w[h] = act ? __expf(a0[h] - mh[h]) * es / dh[h] : 0.f;
    }
    int rowid = act ? (myt * N_NODES + src) : 0;

    /* ---- serial accumulate over chunk0 edges: lanes = 4 channels each ---- */
    float4 acc = make_float4(0.f, 0.f, 0.f, 0.f);
    int lim = min(total, 32);
#pragma unroll 4
    for (int q = 0; q < lim; q++) {
        int   r  = __shfl_sync(FULL, rowid, q);
        float w0 = __shfl_sync(FULL, w[0], q);
        float w1 = __shfl_sync(FULL, w[1], q);
        float w2 = __shfl_sync(FULL, w[2], q);
        float w3 = __shfl_sync(FULL, w[3], q);
        float ww = hl == 0 ? w0 : hl == 1 ? w1 : hl == 2 ? w2 : w3;
        float4 xv = ((const float4*)(g_xt + ((size_t)r << 7)))[lane];
        acc.x += ww * xv.x;
        acc.y += ww * xv.y;
        acc.z += ww * xv.z;
        acc.w += ww * xv.w;
    }

    /* rare extras: serial, per-edge recompute (broadcast loads) */
#pragma unroll 1
    for (int q = 32; q < total; q++) {
        int t = (q < p1) ? 0 : (q < p2) ? 1 : (q < p3) ? 2 : 3;
        int b = (q < p1) ? 0 : (q < p2) ? p1 : (q < p3) ? p2 : p3;
        int s = g_rec[(((size_t)dst * 4 + t) << 7) + (q - b)];
        const float* sirow = g_si + ((size_t)t * N_NODES + dst) * S_PAD + hl * 5;
        const float* sjrow = g_sj + ((size_t)t * N_NODES + s) * S_PAD + hl * 5;
        float aa = 0.f;
#pragma unroll
        for (int k = 0; k < N_CONF; k++) {
            float v = sirow[k] + sjrow[k];
            v = (v > 0.f) ? v : 0.2f * v;
            aa += pk[k] * v;
        }
        float msel = (t == 0 ? m_arr[hl] : t == 1 ? m_arr[4 + hl]
                    : t == 2 ? m_arr[8 + hl] : m_arr[12 + hl]);
        float dsel = (t == 0 ? d_arr[hl] : t == 1 ? d_arr[4 + hl]
                    : t == 2 ? d_arr[8 + hl] : d_arr[12 + hl]);
        float ww = __expf(aa - msel) * sel4(eim, t) / dsel;
        float4 xv = ((const float4*)(g_xt + (((size_t)t * N_NODES + s) << 7)))[lane];
        acc.x += ww * xv.x;
        acc.y += ww * xv.y;
        acc.z += ww * xv.z;
        acc.w += ww * xv.w;
    }

    /* epilogue: + x @ W[0] (= xt[0,dst]) + bias */
    float4 self = ((const float4*)(g_xt + ((size_t)dst << 7)))[lane];
    float4 bb   = ((const float4*)bias)[lane];
    float4 o;
    o.x = acc.x + self.x + bb.x;
    o.y = acc.y + self.y + bb.y;
    o.z = acc.z + self.z + bb.z;
    o.w = acc.w + self.w + bb.w;
    ((float4*)(out + (size_t)dst * D_OUT))[lane] = o;
}

/* ============================================================================ */
extern "C" void kernel_launch(void* const* d_in, const int* in_sizes, int n_in,
                              void* d_out, int out_size) {
    const float* x    = (const float*)d_in[0];
    const int*   ei   = (const int*)d_in[1];
    const int*   et   = (const int*)d_in[2];
    const float* W    = (const float*)d_in[3];
    const float* att  = (const float*)d_in[4];
    const float* conf = (const float*)d_in[5];
    const float* eimp = (const float*)d_in[6];
    const float* bias = (const float*)d_in[7];
    float*       out  = (float*)d_out;

    void* cntp = nullptr;
    cudaGetSymbolAddress(&cntp, g_cnt);
    cudaMemsetAsync(cntp, 0, SEG * sizeof(int));

    build_kernel<<<(N_EDGES + 255) / 256, 256>>>(ei, et);
    dim3 gg((N_NODES + 127) / 128, N_TYPES);
    gemm_kernel<<<gg, 256>>>(x, W);
    score_kernel<<<(SEG * HEADS + 255) / 256, 256>>>(att);
    node_kernel<<<(N_NODES * 32 + 255) / 256, 256>>>(conf, eimp, bias, out);
}

// round 4
// speedup vs baseline: 1.2238x; 1.2238x over previous
#include <cuda_runtime.h>
#include <math.h>

#define N_NODES 50000
#define N_EDGES 800000
#define IN_CH 128
#define OUT_CH 32
#define HEADS 4
#define N_TYPES 4
#define N_CONF 5
#define D_OUT 128                 /* HEADS*OUT_CH */
#define SEG (N_TYPES * N_NODES)   /* 200000 (dst,type) segments */
#define SCAN_BLOCKS ((SEG + 1023) / 1024)   /* 196 */
#define SROW 20                   /* floats per (t,n) score row */

/* ------------------------- device scratch (static, no allocation) ---------- */
__device__ float g_xt[(size_t)N_TYPES * N_NODES * D_OUT];          /* 102.4 MB */
__device__ float g_si[(size_t)N_TYPES * N_NODES * SROW];           /* 16 MB */
__device__ float g_sj[(size_t)N_TYPES * N_NODES * SROW];           /* 16 MB */
__device__ int   g_cnt[SEG];
__device__ int   g_offs[SEG + 1];
__device__ int   g_cursor[SEG];
__device__ int   g_rec[N_EDGES];                                   /* 3.2 MB, src|t<<16 */
__device__ int   g_bsum[SCAN_BLOCKS];

/* ------------------------- f32x2 packed FMA helpers ------------------------ */
__device__ __forceinline__ unsigned long long f2dup(float v) {
    unsigned long long r;
    asm("mov.b64 %0, {%1, %1};" : "=l"(r) : "f"(v));
    return r;
}
__device__ __forceinline__ unsigned long long f2pack(float x, float y) {
    unsigned long long r;
    asm("mov.b64 %0, {%1, %2};" : "=l"(r) : "f"(x), "f"(y));
    return r;
}
__device__ __forceinline__ void ffma2(unsigned long long& c, unsigned long long a,
                                      unsigned long long b) {
    asm("fma.rn.f32x2 %0, %1, %2, %0;" : "+l"(c) : "l"(a), "l"(b));
}
__device__ __forceinline__ float2 f2unpack(unsigned long long v) {
    float2 r;
    asm("mov.b64 {%0, %1}, %2;" : "=f"(r.x), "=f"(r.y) : "l"(v));
    return r;
}
__device__ __forceinline__ float sel4(const float* a, int t) {
    return t == 0 ? a[0] : t == 1 ? a[1] : t == 2 ? a[2] : a[3];
}

/* ============================================================================
 * K1: xt[t] = x @ W[t]  (M=50000, K=128, N=128) x 4 types, fp32 via f32x2.
 * ==========================================================================*/
__global__ __launch_bounds__(256) void gemm_kernel(const float* __restrict__ x,
                                                   const float* __restrict__ W) {
    __shared__ float As[32][132];
    __shared__ float Bs[32][128];

    const int t   = blockIdx.y;
    const int n0  = blockIdx.x * 128;
    const int tid = threadIdx.x;
    const int tx  = tid & 15, ty = tid >> 4;
    const float* Wt = W + (size_t)t * IN_CH * D_OUT;

    unsigned long long acc[8][4];
#pragma unroll
    for (int i = 0; i < 8; i++)
#pragma unroll
        for (int j = 0; j < 4; j++) acc[i][j] = 0ULL;

    for (int kc = 0; kc < 4; kc++) {
#pragma unroll
        for (int it = 0; it < 4; it++) {
            int f = tid + it * 256;
            int r = f >> 3, c4 = f & 7;
            int n = n0 + r;
            float4 v = make_float4(0.f, 0.f, 0.f, 0.f);
            if (n < N_NODES)
                v = *(const float4*)(x + (size_t)n * IN_CH + kc * 32 + c4 * 4);
            As[c4 * 4 + 0][r] = v.x;
            As[c4 * 4 + 1][r] = v.y;
            As[c4 * 4 + 2][r] = v.z;
            As[c4 * 4 + 3][r] = v.w;
        }
#pragma unroll
        for (int it = 0; it < 4; it++) {
            int f = tid + it * 256;
            int kk = f >> 5, n4 = f & 31;
            float4 v = *(const float4*)(Wt + (size_t)(kc * 32 + kk) * D_OUT + n4 * 4);
            *(float4*)(&Bs[kk][n4 * 4]) = v;
        }
        __syncthreads();
#pragma unroll
        for (int kk = 0; kk < 32; kk++) {
            float4 a0 = *(const float4*)(&As[kk][ty * 8]);
            float4 a1 = *(const float4*)(&As[kk][ty * 8 + 4]);
            float4 b0 = *(const float4*)(&Bs[kk][tx * 8]);
            float4 b1 = *(const float4*)(&Bs[kk][tx * 8 + 4]);
            unsigned long long bp0 = f2pack(b0.x, b0.y);
            unsigned long long bp1 = f2pack(b0.z, b0.w);
            unsigned long long bp2 = f2pack(b1.x, b1.y);
            unsigned long long bp3 = f2pack(b1.z, b1.w);
            float av[8] = {a0.x, a0.y, a0.z, a0.w, a1.x, a1.y, a1.z, a1.w};
#pragma unroll
            for (int i = 0; i < 8; i++) {
                unsigned long long ad = f2dup(av[i]);
                ffma2(acc[i][0], ad, bp0);
                ffma2(acc[i][1], ad, bp1);
                ffma2(acc[i][2], ad, bp2);
                ffma2(acc[i][3], ad, bp3);
            }
        }
        __syncthreads();
    }
#pragma unroll
    for (int i = 0; i < 8; i++) {
        int n = n0 + ty * 8 + i;
        if (n >= N_NODES) break;
        float* dst = g_xt + ((size_t)t * N_NODES + n) * D_OUT + tx * 8;
        float2 p0 = f2unpack(acc[i][0]), p1 = f2unpack(acc[i][1]);
        float2 p2 = f2unpack(acc[i][2]), p3 = f2unpack(acc[i][3]);
        *(float4*)dst       = make_float4(p0.x, p0.y, p1.x, p1.y);
        *(float4*)(dst + 4) = make_float4(p2.x, p2.y, p3.x, p3.y);
    }
}

/* ============================================================================
 * K2: per-(type,node,head) endpoint scores (row stride 20)
 * ==========================================================================*/
__global__ __launch_bounds__(256) void score_kernel(const float* __restrict__ att) {
    __shared__ float att_s[N_CONF * HEADS * 2 * OUT_CH]; /* 1280 floats */
    for (int i = threadIdx.x; i < N_CONF * HEADS * 2 * OUT_CH; i += 256)
        att_s[i] = att[i];
    __syncthreads();

    int id = blockIdx.x * 256 + threadIdx.x;
    if (id >= SEG * HEADS) return;
    int h  = id & 3;
    int nn = id >> 2;   /* = t*N + n */

    const float4* v4 = (const float4*)(g_xt + (size_t)nn * D_OUT + h * 32);
    float si[5] = {0, 0, 0, 0, 0}, sj[5] = {0, 0, 0, 0, 0};
#pragma unroll
    for (int q = 0; q < 8; q++) {
        float4 v = v4[q];
#pragma unroll
        for (int k = 0; k < N_CONF; k++) {
            float4 ai = ((const float4*)att_s)[(k * HEADS + h) * 16 + q];
            float4 aj = ((const float4*)att_s)[(k * HEADS + h) * 16 + 8 + q];
            si[k] += v.x * ai.x + v.y * ai.y + v.z * ai.z + v.w * ai.w;
            sj[k] += v.x * aj.x + v.y * aj.y + v.z * aj.z + v.w * aj.w;
        }
    }
    float* so_i = g_si + (size_t)nn * SROW + h * N_CONF;
    float* so_j = g_sj + (size_t)nn * SROW + h * N_CONF;
#pragma unroll
    for (int k = 0; k < N_CONF; k++) { so_i[k] = si[k]; so_j[k] = sj[k]; }
}

/* ============================================================================
 * CSR build: histogram -> 3-phase scan -> scatter (packed src|t<<16)
 * ==========================================================================*/
__global__ void hist_kernel(const int* __restrict__ ei, const int* __restrict__ et) {
    int e = blockIdx.x * 256 + threadIdx.x;
    if (e >= N_EDGES) return;
    int d = ei[N_EDGES + e];
    int t = et[e];
    atomicAdd(&g_cnt[d * 4 + t], 1);
}

__device__ __forceinline__ int block_scan_1024(int v, int* smem32, int* tot) {
    int lane = threadIdx.x & 31, w = threadIdx.x >> 5;
    int inc = v;
#pragma unroll
    for (int o = 1; o < 32; o <<= 1) {
        int u = __shfl_up_sync(0xffffffffu, inc, o);
        if (lane >= o) inc += u;
    }
    if (lane == 31) smem32[w] = inc;
    __syncthreads();
    if (w == 0) {
        int ws = smem32[lane];
#pragma unroll
        for (int o = 1; o < 32; o <<= 1) {
            int u = __shfl_up_sync(0xffffffffu, ws, o);
            if (lane >= o) ws += u;
        }
        smem32[lane] = ws;
    }
    __syncthreads();
    int base = (w == 0) ? 0 : smem32[w - 1];
    *tot = smem32[31];
    return inc + base;
}

__global__ __launch_bounds__(1024) void scan_phase1() {
    int idx = blockIdx.x * 1024 + threadIdx.x;
    int v = (idx < SEG) ? g_cnt[idx] : 0;
    __shared__ int smem32[32];
    int tot;
    block_scan_1024(v, smem32, &tot);
    if (threadIdx.x == 0) g_bsum[blockIdx.x] = tot;
}

__global__ __launch_bounds__(256) void scan_phase2() {
    __shared__ int smem32[32];
    int v = (threadIdx.x < SCAN_BLOCKS) ? g_bsum[threadIdx.x] : 0;
    int lane = threadIdx.x & 31, w = threadIdx.x >> 5;
    int inc = v;
#pragma unroll
    for (int o = 1; o < 32; o <<= 1) {
        int u = __shfl_up_sync(0xffffffffu, inc, o);
        if (lane >= o) inc += u;
    }
    if (lane == 31) smem32[w] = inc;
    __syncthreads();
    if (w == 0) {
        int ws = (lane < 8) ? smem32[lane] : 0;
#pragma unroll
        for (int o = 1; o < 8; o <<= 1) {
            int u = __shfl_up_sync(0xffffffffu, ws, o);
            if (lane >= o) ws += u;
        }
        if (lane < 8) smem32[lane] = ws;
    }
    __syncthreads();
    int base = (w == 0) ? 0 : smem32[w - 1];
    int excl = inc + base - v;
    if (threadIdx.x < SCAN_BLOCKS) g_bsum[threadIdx.x] = excl;
}

__global__ __launch_bounds__(1024) void scan_phase3() {
    int idx = blockIdx.x * 1024 + threadIdx.x;
    int v = (idx < SEG) ? g_cnt[idx] : 0;
    __shared__ int smem32[32];
    int tot;
    int inc = block_scan_1024(v, smem32, &tot);
    int excl = inc - v + g_bsum[blockIdx.x];
    if (idx < SEG) {
        g_offs[idx]   = excl;
        g_cursor[idx] = excl;
        if (idx == SEG - 1) g_offs[SEG] = excl + v;
    }
}

__global__ void scatter_kernel(const int* __restrict__ ei, const int* __restrict__ et) {
    int e = blockIdx.x * 256 + threadIdx.x;
    if (e >= N_EDGES) return;
    int src = ei[e];
    int d   = ei[N_EDGES + e];
    int t   = et[e];
    int pos = atomicAdd(&g_cursor[d * 4 + t], 1);
    g_rec[pos] = src | (t << 16);
}

/* ============================================================================
 * K4: one warp per dst node; contiguous packed edge range, smem m/d tables.
 * ==========================================================================*/
__global__ __launch_bounds__(256) void node_kernel(const float* __restrict__ conf,
                                                   const float* __restrict__ eimp,
                                                   const float* __restrict__ bias,
                                                   float* __restrict__ out) {
    const unsigned FULL = 0xffffffffu;
    __shared__ float md[8][32];          /* per warp: [0..15]=m, [16..31]=d */
    int gw   = (blockIdx.x * blockDim.x + threadIdx.x) >> 5;
    int wib  = threadIdx.x >> 5;
    int lane = threadIdx.x & 31;
    if (gw >= N_NODES) return;
    const int dst = gw;
    const int hl  = lane >> 3;

    /* pk = softmax(confounder_probs) */
    float c0 = conf[0], c1 = conf[1], c2 = conf[2], c3 = conf[3], c4 = conf[4];
    float mx = fmaxf(fmaxf(fmaxf(c0, c1), fmaxf(c2, c3)), c4);
    float e0 = __expf(c0 - mx), e1 = __expf(c1 - mx), e2 = __expf(c2 - mx);
    float e3 = __expf(c3 - mx), e4 = __expf(c4 - mx);
    float inv = 1.f / (e0 + e1 + e2 + e3 + e4);
    float pk[5] = {e0 * inv, e1 * inv, e2 * inv, e3 * inv, e4 * inv};
    float eim[4] = {eimp[0], eimp[1], eimp[2], eimp[3]};

    int s0 = g_offs[dst * 4];
    int s1 = g_offs[dst * 4 + 4];
    int total = s1 - s0;

    /* ---- chunk0: one edge per lane (total<=32 covers ~all nodes) ---- */
    bool act = lane < total;
    int pack = act ? g_rec[s0 + lane] : 0;
    int myt  = pack >> 16;
    int src  = pack & 0xFFFF;

    float a0[4];
    {
        const float* sirow = g_si + ((size_t)myt * N_NODES + dst) * SROW;
        const float* sjrow = g_sj + ((size_t)myt * N_NODES + src) * SROW;
        float si[20], sj[20];
#pragma unroll
        for (int q = 0; q < 5; q++) {
            float4 u = ((const float4*)sirow)[q];
            si[q * 4 + 0] = u.x; si[q * 4 + 1] = u.y; si[q * 4 + 2] = u.z; si[q * 4 + 3] = u.w;
            float4 v = ((const float4*)sjrow)[q];
            sj[q * 4 + 0] = v.x; sj[q * 4 + 1] = v.y; sj[q * 4 + 2] = v.z; sj[q * 4 + 3] = v.w;
        }
#pragma unroll
        for (int h = 0; h < 4; h++) {
            float ah = 0.f;
#pragma unroll
            for (int k = 0; k < N_CONF; k++) {
                float v = si[h * 5 + k] + sj[h * 5 + k];
                v = (v > 0.f) ? v : 0.2f * v;
                ah += pk[k] * v;
            }
            a0[h] = ah;
        }
    }

    /* ---- per-(type,head) max across warp -> smem table ---- */
#pragma unroll
    for (int tt = 0; tt < 4; tt++)
#pragma unroll
        for (int hh = 0; hh < 4; hh++) {
            float v = (act && myt == tt) ? a0[hh] : -1e30f;
#pragma unroll
            for (int o = 16; o; o >>= 1) v = fmaxf(v, __shfl_xor_sync(FULL, v, o));
            md[wib][tt * 4 + hh] = v;
        }
    __syncwarp();

    /* rare extras (total > 32): recompute alphas for max */
#pragma unroll 1
    for (int eb = 32; eb < total; eb += 32) {
        bool a2 = eb + lane < total;
        int pk2 = a2 ? g_rec[s0 + eb + lane] : 0;
        int t2 = pk2 >> 16, s2 = pk2 & 0xFFFF;
        const float* sirow = g_si + ((size_t)t2 * N_NODES + dst) * SROW;
        const float* sjrow = g_sj + ((size_t)t2 * N_NODES + s2) * SROW;
        float aa[4];
#pragma unroll
        for (int h = 0; h < 4; h++) {
            float ah = 0.f;
#pragma unroll
            for (int k = 0; k < N_CONF; k++) {
                float v = sirow[h * 5 + k] + sjrow[h * 5 + k];
                v = (v > 0.f) ? v : 0.2f * v;
                ah += pk[k] * v;
            }
            aa[h] = ah;
        }
#pragma unroll
        for (int tt = 0; tt < 4; tt++)
#pragma unroll
            for (int hh = 0; hh < 4; hh++) {
                float v = (a2 && t2 == tt) ? aa[hh] : -1e30f;
#pragma unroll
                for (int o = 16; o; o >>= 1) v = fmaxf(v, __shfl_xor_sync(FULL, v, o));
                if (v > md[wib][tt * 4 + hh]) md[wib][tt * 4 + hh] = v;
            }
        __syncwarp();
    }

    /* ---- per-(type,head) exp-sum -> smem table ---- */
#pragma unroll
    for (int tt = 0; tt < 4; tt++)
#pragma unroll
        for (int hh = 0; hh < 4; hh++) {
            float v = (act && myt == tt) ? __expf(a0[hh] - md[wib][tt * 4 + hh]) : 0.f;
#pragma unroll
            for (int o = 16; o; o >>= 1) v += __shfl_xor_sync(FULL, v, o);
            md[wib][16 + tt * 4 + hh] = v;
        }
    __syncwarp();

#pragma unroll 1
    for (int eb = 32; eb < total; eb += 32) {
        bool a2 = eb + lane < total;
        int pk2 = a2 ? g_rec[s0 + eb + lane] : 0;
        int t2 = pk2 >> 16, s2 = pk2 & 0xFFFF;
        const float* sirow = g_si + ((size_t)t2 * N_NODES + dst) * SROW;
        const float* sjrow = g_sj + ((size_t)t2 * N_NODES + s2) * SROW;
        float aa[4];
#pragma unroll
        for (int h = 0; h < 4; h++) {
            float ah = 0.f;
#pragma unroll
            for (int k = 0; k < N_CONF; k++) {
                float v = sirow[h * 5 + k] + sjrow[h * 5 + k];
                v = (v > 0.f) ? v : 0.2f * v;
                ah += pk[k] * v;
            }
            aa[h] = ah;
        }
#pragma unroll
        for (int tt = 0; tt < 4; tt++)
#pragma unroll
            for (int hh = 0; hh < 4; hh++) {
                float v = (a2 && t2 == tt) ? __expf(aa[hh] - md[wib][tt * 4 + hh]) : 0.f;
#pragma unroll
                for (int o = 16; o; o >>= 1) v += __shfl_xor_sync(FULL, v, o);
                md[wib][16 + tt * 4 + hh] += v;
            }
        __syncwarp();
    }

    /* ---- per-lane normalized weights (chunk0 edges) ---- */
    float w[4];
    {
        float es = sel4(eim, myt);
#pragma unroll
        for (int h = 0; h < 4; h++)
            w[h] = act ? __expf(a0[h] - md[wib][myt * 4 + h]) * es
                          / md[wib][16 + myt * 4 + h]
                       : 0.f;
    }
    int rowid = act ? (myt * N_NODES + src) : 0;

    /* ---- serial accumulate over chunk0 edges: lanes = 4 channels each ---- */
    float4 acc = make_float4(0.f, 0.f, 0.f, 0.f);
    int lim = min(total, 32);
#pragma unroll 4
    for (int q = 0; q < lim; q++) {
        int   r  = __shfl_sync(FULL, rowid, q);
        float w0 = __shfl_sync(FULL, w[0], q);
        float w1 = __shfl_sync(FULL, w[1], q);
        float w2 = __shfl_sync(FULL, w[2], q);
        float w3 = __shfl_sync(FULL, w[3], q);
        float ww = hl == 0 ? w0 : hl == 1 ? w1 : hl == 2 ? w2 : w3;
        float4 xv = ((const float4*)(g_xt + ((size_t)r << 7)))[lane];
        acc.x += ww * xv.x;
        acc.y += ww * xv.y;
        acc.z += ww * xv.z;
        acc.w += ww * xv.w;
    }

    /* rare extras: serial, per-edge recompute */
#pragma unroll 1
    for (int q = 32; q < total; q++) {
        int pk2 = g_rec[s0 + q];
        int t = pk2 >> 16, s = pk2 & 0xFFFF;
        const float* sirow = g_si + ((size_t)t * N_NODES + dst) * SROW + hl * 5;
        const float* sjrow = g_sj + ((size_t)t * N_NODES + s) * SROW + hl * 5;
        float aa = 0.f;
#pragma unroll
        for (int k = 0; k < N_CONF; k++) {
            float v = sirow[k] + sjrow[k];
            v = (v > 0.f) ? v : 0.2f * v;
            aa += pk[k] * v;
        }
        float ww = __expf(aa - md[wib][t * 4 + hl]) * sel4(eim, t)
                   / md[wib][16 + t * 4 + hl];
        float4 xv = ((const float4*)(g_xt + (((size_t)t * N_NODES + s) << 7)))[lane];
        acc.x += ww * xv.x;
        acc.y += ww * xv.y;
        acc.z += ww * xv.z;
        acc.w += ww * xv.w;
    }

    /* epilogue: + x @ W[0] (= xt[0,dst]) + bias */
    float4 self = ((const float4*)(g_xt + ((size_t)dst << 7)))[lane];
    float4 bb   = ((const float4*)bias)[lane];
    float4 o;
    o.x = acc.x + self.x + bb.x;
    o.y = acc.y + self.y + bb.y;
    o.z = acc.z + self.z + bb.z;
    o.w = acc.w + self.w + bb.w;
    ((float4*)(out + (size_t)dst * D_OUT))[lane] = o;
}

/* ============================================================================ */
extern "C" void kernel_launch(void* const* d_in, const int* in_sizes, int n_in,
                              void* d_out, int out_size) {
    const float* x    = (const float*)d_in[0];
    const int*   ei   = (const int*)d_in[1];
    const int*   et   = (const int*)d_in[2];
    const float* W    = (const float*)d_in[3];
    const float* att  = (const float*)d_in[4];
    const float* conf = (const float*)d_in[5];
    const float* eimp = (const float*)d_in[6];
    const float* bias = (const float*)d_in[7];
    float*       out  = (float*)d_out;

    void* cntp = nullptr;
    cudaGetSymbolAddress(&cntp, g_cnt);
    cudaMemsetAsync(cntp, 0, SEG * sizeof(int));

    hist_kernel<<<(N_EDGES + 255) / 256, 256>>>(ei, et);
    scan_phase1<<<SCAN_BLOCKS, 1024>>>();
    scan_phase2<<<1, 256>>>();
    scan_phase3<<<SCAN_BLOCKS, 1024>>>();
    scatter_kernel<<<(N_EDGES + 255) / 256, 256>>>(ei, et);

    dim3 gg((N_NODES + 127) / 128, N_TYPES);
    gemm_kernel<<<gg, 256>>>(x, W);
    score_kernel<<<(SEG * HEADS + 255) / 256, 256>>>(att);
    node_kernel<<<(N_NODES * 32 + 255) / 256, 256>>>(conf, eimp, bias, out);
}

// round 5
// speedup vs baseline: 1.3265x; 1.0840x over previous
#include <cuda_runtime.h>
#include <math.h>

#define N_NODES 50000
#define N_EDGES 800000
#define IN_CH 128
#define OUT_CH 32
#define HEADS 4
#define N_TYPES 4
#define N_CONF 5
#define D_OUT 128                 /* HEADS*OUT_CH */
#define SEG (N_TYPES * N_NODES)   /* 200000 (dst,type) segments */
#define SCAN_BLOCKS ((SEG + 1023) / 1024)   /* 196 */
#define SROW 20                   /* floats per (t,n) score row */

/* ------------------------- device scratch (static, no allocation) ---------- */
__device__ float g_xt[(size_t)N_TYPES * N_NODES * D_OUT];          /* 102.4 MB */
__device__ float g_si[(size_t)N_TYPES * N_NODES * SROW];           /* 16 MB */
__device__ float g_sj[(size_t)N_TYPES * N_NODES * SROW];           /* 16 MB */
__device__ int   g_cnt[SEG];
__device__ int   g_offs[SEG + 1];
__device__ int   g_cursor[SEG];
__device__ int   g_rec[N_EDGES];                                   /* 3.2 MB, src|t<<16 */
__device__ int   g_bsum[SCAN_BLOCKS];

/* ------------------------- f32x2 packed FMA helpers ------------------------ */
__device__ __forceinline__ unsigned long long f2dup(float v) {
    unsigned long long r;
    asm("mov.b64 %0, {%1, %1};" : "=l"(r) : "f"(v));
    return r;
}
__device__ __forceinline__ unsigned long long f2pack(float x, float y) {
    unsigned long long r;
    asm("mov.b64 %0, {%1, %2};" : "=l"(r) : "f"(x), "f"(y));
    return r;
}
__device__ __forceinline__ void ffma2(unsigned long long& c, unsigned long long a,
                                      unsigned long long b) {
    asm("fma.rn.f32x2 %0, %1, %2, %0;" : "+l"(c) : "l"(a), "l"(b));
}
__device__ __forceinline__ float2 f2unpack(unsigned long long v) {
    float2 r;
    asm("mov.b64 {%0, %1}, %2;" : "=f"(r.x), "=f"(r.y) : "l"(v));
    return r;
}
__device__ __forceinline__ float sel4(const float* a, int t) {
    return t == 0 ? a[0] : t == 1 ? a[1] : t == 2 ? a[2] : a[3];
}

/* ============================================================================
 * K1: xt[t] = x @ W[t]  (M=50000, K=128, N=128) x 4 types, fp32 via f32x2.
 * ==========================================================================*/
__global__ __launch_bounds__(256) void gemm_kernel(const float* __restrict__ x,
                                                   const float* __restrict__ W) {
    __shared__ float As[32][132];
    __shared__ float Bs[32][128];

    const int t   = blockIdx.y;
    const int n0  = blockIdx.x * 128;
    const int tid = threadIdx.x;
    const int tx  = tid & 15, ty = tid >> 4;
    const float* Wt = W + (size_t)t * IN_CH * D_OUT;

    unsigned long long acc[8][4];
#pragma unroll
    for (int i = 0; i < 8; i++)
#pragma unroll
        for (int j = 0; j < 4; j++) acc[i][j] = 0ULL;

    for (int kc = 0; kc < 4; kc++) {
#pragma unroll
        for (int it = 0; it < 4; it++) {
            int f = tid + it * 256;
            int r = f >> 3, c4 = f & 7;
            int n = n0 + r;
            float4 v = make_float4(0.f, 0.f, 0.f, 0.f);
            if (n < N_NODES)
                v = *(const float4*)(x + (size_t)n * IN_CH + kc * 32 + c4 * 4);
            As[c4 * 4 + 0][r] = v.x;
            As[c4 * 4 + 1][r] = v.y;
            As[c4 * 4 + 2][r] = v.z;
            As[c4 * 4 + 3][r] = v.w;
        }
#pragma unroll
        for (int it = 0; it < 4; it++) {
            int f = tid + it * 256;
            int kk = f >> 5, n4 = f & 31;
            float4 v = *(const float4*)(Wt + (size_t)(kc * 32 + kk) * D_OUT + n4 * 4);
            *(float4*)(&Bs[kk][n4 * 4]) = v;
        }
        __syncthreads();
#pragma unroll
        for (int kk = 0; kk < 32; kk++) {
            float4 a0 = *(const float4*)(&As[kk][ty * 8]);
            float4 a1 = *(const float4*)(&As[kk][ty * 8 + 4]);
            float4 b0 = *(const float4*)(&Bs[kk][tx * 8]);
            float4 b1 = *(const float4*)(&Bs[kk][tx * 8 + 4]);
            unsigned long long bp0 = f2pack(b0.x, b0.y);
            unsigned long long bp1 = f2pack(b0.z, b0.w);
            unsigned long long bp2 = f2pack(b1.x, b1.y);
            unsigned long long bp3 = f2pack(b1.z, b1.w);
            float av[8] = {a0.x, a0.y, a0.z, a0.w, a1.x, a1.y, a1.z, a1.w};
#pragma unroll
            for (int i = 0; i < 8; i++) {
                unsigned long long ad = f2dup(av[i]);
                ffma2(acc[i][0], ad, bp0);
                ffma2(acc[i][1], ad, bp1);
                ffma2(acc[i][2], ad, bp2);
                ffma2(acc[i][3], ad, bp3);
            }
        }
        __syncthreads();
    }
#pragma unroll
    for (int i = 0; i < 8; i++) {
        int n = n0 + ty * 8 + i;
        if (n >= N_NODES) break;
        float* dst = g_xt + ((size_t)t * N_NODES + n) * D_OUT + tx * 8;
        float2 p0 = f2unpack(acc[i][0]), p1 = f2unpack(acc[i][1]);
        float2 p2 = f2unpack(acc[i][2]), p3 = f2unpack(acc[i][3]);
        *(float4*)dst       = make_float4(p0.x, p0.y, p1.x, p1.y);
        *(float4*)(dst + 4) = make_float4(p2.x, p2.y, p3.x, p3.y);
    }
}

/* ============================================================================
 * K2: per-(type,node,head) endpoint scores (row stride 20)
 * ==========================================================================*/
__global__ __launch_bounds__(256) void score_kernel(const float* __restrict__ att) {
    __shared__ float att_s[N_CONF * HEADS * 2 * OUT_CH]; /* 1280 floats */
    for (int i = threadIdx.x; i < N_CONF * HEADS * 2 * OUT_CH; i += 256)
        att_s[i] = att[i];
    __syncthreads();

    int id = blockIdx.x * 256 + threadIdx.x;
    if (id >= SEG * HEADS) return;
    int h  = id & 3;
    int nn = id >> 2;   /* = t*N + n */

    const float4* v4 = (const float4*)(g_xt + (size_t)nn * D_OUT + h * 32);
    float si[5] = {0, 0, 0, 0, 0}, sj[5] = {0, 0, 0, 0, 0};
#pragma unroll
    for (int q = 0; q < 8; q++) {
        float4 v = v4[q];
#pragma unroll
        for (int k = 0; k < N_CONF; k++) {
            float4 ai = ((const float4*)att_s)[(k * HEADS + h) * 16 + q];
            float4 aj = ((const float4*)att_s)[(k * HEADS + h) * 16 + 8 + q];
            si[k] += v.x * ai.x + v.y * ai.y + v.z * ai.z + v.w * ai.w;
            sj[k] += v.x * aj.x + v.y * aj.y + v.z * aj.z + v.w * aj.w;
        }
    }
    float* so_i = g_si + (size_t)nn * SROW + h * N_CONF;
    float* so_j = g_sj + (size_t)nn * SROW + h * N_CONF;
#pragma unroll
    for (int k = 0; k < N_CONF; k++) { so_i[k] = si[k]; so_j[k] = sj[k]; }
}

/* ============================================================================
 * CSR build: histogram -> 3-phase scan -> scatter (packed src|t<<16)
 * ==========================================================================*/
__global__ void hist_kernel(const int* __restrict__ ei, const int* __restrict__ et) {
    int e = blockIdx.x * 256 + threadIdx.x;
    if (e >= N_EDGES) return;
    int d = ei[N_EDGES + e];
    int t = et[e];
    atomicAdd(&g_cnt[d * 4 + t], 1);
}

__device__ __forceinline__ int block_scan_1024(int v, int* smem32, int* tot) {
    int lane = threadIdx.x & 31, w = threadIdx.x >> 5;
    int inc = v;
#pragma unroll
    for (int o = 1; o < 32; o <<= 1) {
        int u = __shfl_up_sync(0xffffffffu, inc, o);
        if (lane >= o) inc += u;
    }
    if (lane == 31) smem32[w] = inc;
    __syncthreads();
    if (w == 0) {
        int ws = smem32[lane];
#pragma unroll
        for (int o = 1; o < 32; o <<= 1) {
            int u = __shfl_up_sync(0xffffffffu, ws, o);
            if (lane >= o) ws += u;
        }
        smem32[lane] = ws;
    }
    __syncthreads();
    int base = (w == 0) ? 0 : smem32[w - 1];
    *tot = smem32[31];
    return inc + base;
}

__global__ __launch_bounds__(1024) void scan_phase1() {
    int idx = blockIdx.x * 1024 + threadIdx.x;
    int v = (idx < SEG) ? g_cnt[idx] : 0;
    __shared__ int smem32[32];
    int tot;
    block_scan_1024(v, smem32, &tot);
    if (threadIdx.x == 0) g_bsum[blockIdx.x] = tot;
}

__global__ __launch_bounds__(256) void scan_phase2() {
    __shared__ int smem32[32];
    int v = (threadIdx.x < SCAN_BLOCKS) ? g_bsum[threadIdx.x] : 0;
    int lane = threadIdx.x & 31, w = threadIdx.x >> 5;
    int inc = v;
#pragma unroll
    for (int o = 1; o < 32; o <<= 1) {
        int u = __shfl_up_sync(0xffffffffu, inc, o);
        if (lane >= o) inc += u;
    }
    if (lane == 31) smem32[w] = inc;
    __syncthreads();
    if (w == 0) {
        int ws = (lane < 8) ? smem32[lane] : 0;
#pragma unroll
        for (int o = 1; o < 8; o <<= 1) {
            int u = __shfl_up_sync(0xffffffffu, ws, o);
            if (lane >= o) ws += u;
        }
        if (lane < 8) smem32[lane] = ws;
    }
    __syncthreads();
    int base = (w == 0) ? 0 : smem32[w - 1];
    int excl = inc + base - v;
    if (threadIdx.x < SCAN_BLOCKS) g_bsum[threadIdx.x] = excl;
}

__global__ __launch_bounds__(1024) void scan_phase3() {
    int idx = blockIdx.x * 1024 + threadIdx.x;
    int v = (idx < SEG) ? g_cnt[idx] : 0;
    __shared__ int smem32[32];
    int tot;
    int inc = block_scan_1024(v, smem32, &tot);
    int excl = inc - v + g_bsum[blockIdx.x];
    if (idx < SEG) {
        g_offs[idx]   = excl;
        g_cursor[idx] = excl;
        if (idx == SEG - 1) g_offs[SEG] = excl + v;
    }
}

__global__ void scatter_kernel(const int* __restrict__ ei, const int* __restrict__ et) {
    int e = blockIdx.x * 256 + threadIdx.x;
    if (e >= N_EDGES) return;
    int src = ei[e];
    int d   = ei[N_EDGES + e];
    int t   = et[e];
    int pos = atomicAdd(&g_cursor[d * 4 + t], 1);
    g_rec[pos] = src | (t << 16);
}

/* ============================================================================
 * K4: one warp per dst node.
 * Fast path (degree<=32): shared per-head max, per-(type,head) denominators
 * via warp prefix-scan + ballot boundaries, smem-fed accumulate loop.
 * Slow path (degree>32, ~1e-4 of nodes): full per-(type,head) two-pass.
 * ==========================================================================*/
__global__ __launch_bounds__(256) void node_kernel(const float* __restrict__ conf,
                                                   const float* __restrict__ eimp,
                                                   const float* __restrict__ bias,
                                                   float* __restrict__ out) {
    const unsigned FULL = 0xffffffffu;
    __shared__ float w_s[8][32][4];
    __shared__ int   r_s[8][32];
    __shared__ float md[8][32];          /* slow path m/d table */
    int gw   = (blockIdx.x * blockDim.x + threadIdx.x) >> 5;
    int wib  = threadIdx.x >> 5;
    int lane = threadIdx.x & 31;
    if (gw >= N_NODES) return;
    const int dst = gw;
    const int hl  = lane >> 3;

    /* pk = softmax(confounder_probs) */
    float c0 = conf[0], c1 = conf[1], c2 = conf[2], c3 = conf[3], c4 = conf[4];
    float mx = fmaxf(fmaxf(fmaxf(c0, c1), fmaxf(c2, c3)), c4);
    float e0 = __expf(c0 - mx), e1 = __expf(c1 - mx), e2 = __expf(c2 - mx);
    float e3 = __expf(c3 - mx), e4 = __expf(c4 - mx);
    float inv = 1.f / (e0 + e1 + e2 + e3 + e4);
    float pk[5] = {e0 * inv, e1 * inv, e2 * inv, e3 * inv, e4 * inv};
    float eim[4] = {eimp[0], eimp[1], eimp[2], eimp[3]};

    int s0 = g_offs[dst * 4];
    int s1 = g_offs[dst * 4 + 4];
    int total = s1 - s0;

    float4 acc = make_float4(0.f, 0.f, 0.f, 0.f);

    if (total <= 32) {
        /* ------------------------------ FAST PATH ------------------------ */
        bool act = lane < total;
        int pack = act ? g_rec[s0 + lane] : 0;
        int myt  = pack >> 16;
        int src  = pack & 0xFFFF;

        float a0[4];
        {
            const float4* sip = (const float4*)(g_si + ((size_t)myt * N_NODES + dst) * SROW);
            const float4* sjp = (const float4*)(g_sj + ((size_t)myt * N_NODES + src) * SROW);
            float si[20], sj[20];
#pragma unroll
            for (int q = 0; q < 5; q++) {
                float4 u = sip[q];
                si[q * 4 + 0] = u.x; si[q * 4 + 1] = u.y; si[q * 4 + 2] = u.z; si[q * 4 + 3] = u.w;
                float4 v = sjp[q];
                sj[q * 4 + 0] = v.x; sj[q * 4 + 1] = v.y; sj[q * 4 + 2] = v.z; sj[q * 4 + 3] = v.w;
            }
#pragma unroll
            for (int h = 0; h < 4; h++) {
                float ah = 0.f;
#pragma unroll
                for (int k = 0; k < N_CONF; k++) {
                    float v = si[h * 5 + k] + sj[h * 5 + k];
                    v = (v > 0.f) ? v : 0.2f * v;
                    ah += pk[k] * v;
                }
                a0[h] = ah;
            }
        }

        /* per-head GLOBAL max across warp (softmax invariant to shift) */
        float m[4];
#pragma unroll
        for (int h = 0; h < 4; h++) {
            float v = act ? a0[h] : -1e30f;
#pragma unroll
            for (int o = 16; o; o >>= 1) v = fmaxf(v, __shfl_xor_sync(FULL, v, o));
            m[h] = v;
        }

        /* exp + inclusive prefix scan per head */
        float e[4], P[4];
#pragma unroll
        for (int h = 0; h < 4; h++) {
            e[h] = act ? __expf(a0[h] - m[h]) : 0.f;
            P[h] = e[h];
#pragma unroll
            for (int o = 1; o < 32; o <<= 1) {
                float u = __shfl_up_sync(FULL, P[h], o);
                if (lane >= o) P[h] += u;
            }
        }

        /* segment boundaries for my type via ballot */
        unsigned b0m = __ballot_sync(FULL, act && myt == 0);
        unsigned b1m = __ballot_sync(FULL, act && myt == 1);
        unsigned b2m = __ballot_sync(FULL, act && myt == 2);
        unsigned b3m = __ballot_sync(FULL, act && myt == 3);
        unsigned bmy = myt == 0 ? b0m : myt == 1 ? b1m : myt == 2 ? b2m : b3m;
        int hi = (31 - __clz(bmy | 1u)) & 31;   /* last lane of my segment */
        int lo = __ffs(bmy) - 1;                /* first lane of my segment */

        float es = sel4(eim, myt);
        float w[4];
#pragma unroll
        for (int h = 0; h < 4; h++) {
            float ph = __shfl_sync(FULL, P[h], hi);
            float pl = __shfl_sync(FULL, P[h], (lo - 1) & 31);
            float dh = ph - (lo > 0 ? pl : 0.f);
            w[h] = act ? e[h] * es / dh : 0.f;
        }

        /* stash weights + rowids in smem, then channel-parallel accumulate */
        *(float4*)&w_s[wib][lane][0] = make_float4(w[0], w[1], w[2], w[3]);
        r_s[wib][lane] = myt * N_NODES + src;
        __syncwarp();

#pragma unroll 4
        for (int q = 0; q < total; q++) {
            int   r  = r_s[wib][q];
            float ww = w_s[wib][q][hl];
            float4 xv = ((const float4*)(g_xt + ((size_t)r << 7)))[lane];
            acc.x += ww * xv.x;
            acc.y += ww * xv.y;
            acc.z += ww * xv.z;
            acc.w += ww * xv.w;
        }
    } else {
        /* ------------------------------ SLOW PATH ------------------------ */
        bool act = lane < total;
        int pack = act ? g_rec[s0 + lane] : 0;
        int myt  = pack >> 16;
        int src  = pack & 0xFFFF;

        float a0[4];
        {
            const float* sirow = g_si + ((size_t)myt * N_NODES + dst) * SROW;
            const float* sjrow = g_sj + ((size_t)myt * N_NODES + src) * SROW;
#pragma unroll
            for (int h = 0; h < 4; h++) {
                float ah = 0.f;
#pragma unroll
                for (int k = 0; k < N_CONF; k++) {
                    float v = sirow[h * 5 + k] + sjrow[h * 5 + k];
                    v = (v > 0.f) ? v : 0.2f * v;
                    ah += pk[k] * v;
                }
                a0[h] = ah;
            }
        }
#pragma unroll
        for (int tt = 0; tt < 4; tt++)
#pragma unroll
            for (int hh = 0; hh < 4; hh++) {
                float v = (act && myt == tt) ? a0[hh] : -1e30f;
#pragma unroll
                for (int o = 16; o; o >>= 1) v = fmaxf(v, __shfl_xor_sync(FULL, v, o));
                md[wib][tt * 4 + hh] = v;
            }
        __syncwarp();
#pragma unroll 1
        for (int eb = 32; eb < total; eb += 32) {
            bool a2 = eb + lane < total;
            int pk2 = a2 ? g_rec[s0 + eb + lane] : 0;
            int t2 = pk2 >> 16, s2 = pk2 & 0xFFFF;
            const float* sirow = g_si + ((size_t)t2 * N_NODES + dst) * SROW;
            const float* sjrow = g_sj + ((size_t)t2 * N_NODES + s2) * SROW;
            float aa[4];
#pragma unroll
            for (int h = 0; h < 4; h++) {
                float ah = 0.f;
#pragma unroll
                for (int k = 0; k < N_CONF; k++) {
                    float v = sirow[h * 5 + k] + sjrow[h * 5 + k];
                    v = (v > 0.f) ? v : 0.2f * v;
                    ah += pk[k] * v;
                }
                aa[h] = ah;
            }
#pragma unroll
            for (int tt = 0; tt < 4; tt++)
#pragma unroll
                for (int hh = 0; hh < 4; hh++) {
                    float v = (a2 && t2 == tt) ? aa[hh] : -1e30f;
#pragma unroll
                    for (int o = 16; o; o >>= 1) v = fmaxf(v, __shfl_xor_sync(FULL, v, o));
                    if (v > md[wib][tt * 4 + hh]) md[wib][tt * 4 + hh] = v;
                }
            __syncwarp();
        }
#pragma unroll
        for (int tt = 0; tt < 4; tt++)
#pragma unroll
            for (int hh = 0; hh < 4; hh++) {
                float v = (act && myt == tt) ? __expf(a0[hh] - md[wib][tt * 4 + hh]) : 0.f;
#pragma unroll
                for (int o = 16; o; o >>= 1) v += __shfl_xor_sync(FULL, v, o);
                md[wib][16 + tt * 4 + hh] = v;
            }
        __syncwarp();
#pragma unroll 1
        for (int eb = 32; eb < total; eb += 32) {
            bool a2 = eb + lane < total;
            int pk2 = a2 ? g_rec[s0 + eb + lane] : 0;
            int t2 = pk2 >> 16, s2 = pk2 & 0xFFFF;
            const float* sirow = g_si + ((size_t)t2 * N_NODES + dst) * SROW;
            const float* sjrow = g_sj + ((size_t)t2 * N_NODES + s2) * SROW;
            float aa[4];
#pragma unroll
            for (int h = 0; h < 4; h++) {
                float ah = 0.f;
#pragma unroll
                for (int k = 0; k < N_CONF; k++) {
                    float v = sirow[h * 5 + k] + sjrow[h * 5 + k];
                    v = (v > 0.f) ? v : 0.2f * v;
                    ah += pk[k] * v;
                }
                aa[h] = ah;
            }
#pragma unroll
            for (int tt = 0; tt < 4; tt++)
#pragma unroll
                for (int hh = 0; hh < 4; hh++) {
                    float v = (a2 && t2 == tt) ? __expf(aa[hh] - md[wib][tt * 4 + hh]) : 0.f;
#pragma unroll
                    for (int o = 16; o; o >>= 1) v += __shfl_xor_sync(FULL, v, o);
                    md[wib][16 + tt * 4 + hh] += v;
                }
            __syncwarp();
        }
        /* serial accumulate over ALL edges with per-edge recompute */
#pragma unroll 1
        for (int q = 0; q < total; q++) {
            int pk2 = g_rec[s0 + q];
            int t = pk2 >> 16, s = pk2 & 0xFFFF;
            const float* sirow = g_si + ((size_t)t * N_NODES + dst) * SROW + hl * 5;
            const float* sjrow = g_sj + ((size_t)t * N_NODES + s) * SROW + hl * 5;
            float aa = 0.f;
#pragma unroll
            for (int k = 0; k < N_CONF; k++) {
                float v = sirow[k] + sjrow[k];
                v = (v > 0.f) ? v : 0.2f * v;
                aa += pk[k] * v;
            }
            float ww = __expf(aa - md[wib][t * 4 + hl]) * sel4(eim, t)
                       / md[wib][16 + t * 4 + hl];
            float4 xv = ((const float4*)(g_xt + (((size_t)t * N_NODES + s) << 7)))[lane];
            acc.x += ww * xv.x;
            acc.y += ww * xv.y;
            acc.z += ww * xv.z;
            acc.w += ww * xv.w;
        }
    }

    /* epilogue: + x @ W[0] (= xt[0,dst]) + bias */
    float4 self = ((const float4*)(g_xt + ((size_t)dst << 7)))[lane];
    float4 bb   = ((const float4*)bias)[lane];
    float4 o;
    o.x = acc.x + self.x + bb.x;
    o.y = acc.y + self.y + bb.y;
    o.z = acc.z + self.z + bb.z;
    o.w = acc.w + self.w + bb.w;
    ((float4*)(out + (size_t)dst * D_OUT))[lane] = o;
}

/* ============================================================================ */
extern "C" void kernel_launch(void* const* d_in, const int* in_sizes, int n_in,
                              void* d_out, int out_size) {
    const float* x    = (const float*)d_in[0];
    const int*   ei   = (const int*)d_in[1];
    const int*   et   = (const int*)d_in[2];
    const float* W    = (const float*)d_in[3];
    const float* att  = (const float*)d_in[4];
    const float* conf = (const float*)d_in[5];
    const float* eimp = (const float*)d_in[6];
    const float* bias = (const float*)d_in[7];
    float*       out  = (float*)d_out;

    void* cntp = nullptr;
    cudaGetSymbolAddress(&cntp, g_cnt);
    cudaMemsetAsync(cntp, 0, SEG * sizeof(int));

    hist_kernel<<<(N_EDGES + 255) / 256, 256>>>(ei, et);
    scan_phase1<<<SCAN_BLOCKS, 1024>>>();
    scan_phase2<<<1, 256>>>();
    scan_phase3<<<SCAN_BLOCKS, 1024>>>();
    scatter_kernel<<<(N_EDGES + 255) / 256, 256>>>(ei, et);

    dim3 gg((N_NODES + 127) / 128, N_TYPES);
    gemm_kernel<<<gg, 256>>>(x, W);
    score_kernel<<<(SEG * HEADS + 255) / 256, 256>>>(att);
    node_kernel<<<(N_NODES * 32 + 255) / 256, 256>>>(conf, eimp, bias, out);
}

// round 7
// speedup vs baseline: 1.4120x; 1.0644x over previous
#include <cuda_runtime.h>
#include <cuda_bf16.h>
#include <cstdint>
#include <math.h>

#define N_NODES 50000
#define N_EDGES 800000
#define IN_CH 128
#define OUT_CH 32
#define HEADS 4
#define N_TYPES 4
#define N_CONF 5
#define D_OUT 128                 /* HEADS*OUT_CH */
#define SEG (N_TYPES * N_NODES)   /* 200000 (dst,type) segments */
#define SCAN_BLOCKS ((SEG + 1023) / 1024)   /* 196 */
#define SROW 20                   /* floats per (t,n) score row */

/* ------------------------- device scratch (static, no allocation) ---------- */
__device__ float g_xt[(size_t)N_TYPES * N_NODES * D_OUT];          /* 102.4 MB */
__device__ float g_si[(size_t)N_TYPES * N_NODES * SROW];           /* 16 MB */
__device__ float g_sj[(size_t)N_TYPES * N_NODES * SROW];           /* 16 MB */
__device__ int   g_cnt[SEG];
__device__ int   g_offs[SEG + 1];
__device__ int   g_cursor[SEG];
__device__ int   g_rec[N_EDGES];                                   /* 3.2 MB, src|t<<16 */
__device__ int   g_bsum[SCAN_BLOCKS];
__device__ __nv_bfloat16 g_wh[(size_t)N_TYPES * D_OUT * IN_CH];    /* [t][o][k] */
__device__ __nv_bfloat16 g_wl[(size_t)N_TYPES * D_OUT * IN_CH];

__device__ __forceinline__ uint32_t smem_u32(const void* p) {
    uint32_t a;
    asm("{ .reg .u64 t; cvta.to.shared.u64 t, %1; cvt.u32.u64 %0, t; }"
        : "=r"(a) : "l"(p));
    return a;
}
__device__ __forceinline__ float sel4(const float* a, int t) {
    return t == 0 ? a[0] : t == 1 ? a[1] : t == 2 ? a[2] : a[3];
}

/* ============================================================================
 * K0: split + transpose W: [t][k][o] fp32 -> [t][o][k] bf16 hi/lo
 * ==========================================================================*/
__global__ __launch_bounds__(256) void split_w_kernel(const float* __restrict__ W) {
    int i = blockIdx.x * 256 + threadIdx.x;
    if (i >= N_TYPES * IN_CH * D_OUT) return;
    int t = i >> 14, rem = i & 16383, k = rem >> 7, o = rem & 127;
    float v = W[i];
    __nv_bfloat16 h = __float2bfloat16(v);
    __nv_bfloat16 l = __float2bfloat16(v - __bfloat162float(h));
    size_t idx = ((size_t)t * D_OUT + o) * IN_CH + k;
    g_wh[idx] = h;
    g_wl[idx] = l;
}

/* ============================================================================
 * K1: HMMA (mma.sync bf16) GEMM: xt[t] = x @ W[t], 3-term split.
 * CTA: 128x128 tile of one type; 8 warps (4M x 2N), warp tile 32x64.
 * smem row stride 136 bf16 (272 B) -> conflict-free ldmatrix.
 * ==========================================================================*/
#define TSTR 136                       /* bf16 per smem row */
#define SM_TILE (128 * TSTR * 2)       /* 34816 B per tile */
#define SMA_H 0
#define SMA_L (SM_TILE)
#define SMB_H (2 * SM_TILE)
#define SMB_L (3 * SM_TILE)
#define SM_GEMM_TOTAL (4 * SM_TILE)    /* 139264 B */

__device__ __forceinline__ void ldm_x4(uint32_t addr, uint32_t* r) {
    asm volatile("ldmatrix.sync.aligned.m8n8.x4.shared.b16 {%0,%1,%2,%3}, [%4];"
                 : "=r"(r[0]), "=r"(r[1]), "=r"(r[2]), "=r"(r[3]) : "r"(addr));
}
__device__ __forceinline__ void mma_bf16(float* c, const uint32_t* a, const uint32_t* b) {
    asm volatile(
        "mma.sync.aligned.m16n8k16.row.col.f32.bf16.bf16.f32 "
        "{%0,%1,%2,%3}, {%4,%5,%6,%7}, {%8,%9}, {%0,%1,%2,%3};"
        : "+f"(c[0]), "+f"(c[1]), "+f"(c[2]), "+f"(c[3])
        : "r"(a[0]), "r"(a[1]), "r"(a[2]), "r"(a[3]), "r"(b[0]), "r"(b[1]));
}

__global__ __launch_bounds__(256) void gemm_mma_kernel(const float* __restrict__ x) {
    extern __shared__ char smem[];
    uint32_t sb = smem_u32(smem);
    const int tid  = threadIdx.x;
    const int wid  = tid >> 5, lane = tid & 31;
    const int n0   = blockIdx.x * 128;
    const int t    = blockIdx.y;
    const int wm   = wid & 3, wn = wid >> 2;
    const int RM   = wm * 32, CN = wn * 64;

    /* ---- load A (x rows, split hi/lo on the fly) ---- */
    for (int f = tid; f < 4096; f += 256) {
        int row = f >> 5, c4 = f & 31;
        float4 v = make_float4(0.f, 0.f, 0.f, 0.f);
        if (n0 + row < N_NODES)
            v = *(const float4*)(x + (size_t)(n0 + row) * IN_CH + c4 * 4);
        __nv_bfloat16 h[4], l[4];
        float ff[4] = {v.x, v.y, v.z, v.w};
#pragma unroll
        for (int q = 0; q < 4; q++) {
            h[q] = __float2bfloat16(ff[q]);
            l[q] = __float2bfloat16(ff[q] - __bfloat162float(h[q]));
        }
        uint32_t off = (uint32_t)row * (TSTR * 2) + c4 * 8;
        *(uint2*)(smem + SMA_H + off) = *(uint2*)h;
        *(uint2*)(smem + SMA_L + off) = *(uint2*)l;
    }
    /* ---- load B (W_t^T, already split, [o][k] bf16 rows of 256B) ---- */
    for (int f = tid; f < 2048; f += 256) {
        int o = f >> 4, c8 = f & 15;
        uint32_t off = (uint32_t)o * (TSTR * 2) + c8 * 16;
        *(uint4*)(smem + SMB_H + off) =
            *(const uint4*)(g_wh + ((size_t)t * D_OUT + o) * IN_CH + c8 * 8);
        *(uint4*)(smem + SMB_L + off) =
            *(const uint4*)(g_wl + ((size_t)t * D_OUT + o) * IN_CH + c8 * 8);
    }
    __syncthreads();

    /* per-lane ldmatrix base addresses */
    int a_row = RM + ((lane >> 3) & 1) * 8 + (lane & 7);
    int a_c8  = (lane >> 4) * 8;
    uint32_t aH = sb + SMA_H + a_row * (TSTR * 2) + a_c8 * 2;
    uint32_t aL = sb + SMA_L + a_row * (TSTR * 2) + a_c8 * 2;
    int b_row = CN + (lane >> 4) * 8 + (lane & 7);
    int b_c8  = ((lane >> 3) & 1) * 8;
    uint32_t bH = sb + SMB_H + b_row * (TSTR * 2) + b_c8 * 2;
    uint32_t bL = sb + SMB_L + b_row * (TSTR * 2) + b_c8 * 2;

    float acc[2][8][4];
#pragma unroll
    for (int mi = 0; mi < 2; mi++)
#pragma unroll
        for (int ni = 0; ni < 8; ni++)
#pragma unroll
            for (int q = 0; q < 4; q++) acc[mi][ni][q] = 0.f;

#pragma unroll
    for (int kk = 0; kk < 8; kk++) {
        uint32_t ah[2][4], al[2][4], bh[8][2], bl[8][2];
#pragma unroll
        for (int mi = 0; mi < 2; mi++) {
            ldm_x4(aH + mi * 16 * (TSTR * 2) + kk * 32, ah[mi]);
            ldm_x4(aL + mi * 16 * (TSTR * 2) + kk * 32, al[mi]);
        }
#pragma unroll
        for (int p = 0; p < 4; p++) {
            uint32_t rh[4], rl[4];
            ldm_x4(bH + p * 16 * (TSTR * 2) + kk * 32, rh);
            ldm_x4(bL + p * 16 * (TSTR * 2) + kk * 32, rl);
            bh[2 * p][0] = rh[0]; bh[2 * p][1] = rh[1];
            bh[2 * p + 1][0] = rh[2]; bh[2 * p + 1][1] = rh[3];
            bl[2 * p][0] = rl[0]; bl[2 * p][1] = rl[1];
            bl[2 * p + 1][0] = rl[2]; bl[2 * p + 1][1] = rl[3];
        }
#pragma unroll
        for (int mi = 0; mi < 2; mi++)
#pragma unroll
            for (int ni = 0; ni < 8; ni++) {
                mma_bf16(acc[mi][ni], ah[mi], bh[ni]);
                mma_bf16(acc[mi][ni], ah[mi], bl[ni]);
                mma_bf16(acc[mi][ni], al[mi], bh[ni]);
            }
    }

    /* ---- epilogue ---- */
    int qrow = lane >> 2, qcol = (lane & 3) * 2;
#pragma unroll
    for (int mi = 0; mi < 2; mi++) {
        int r0 = n0 + RM + mi * 16 + qrow;
        int r1 = r0 + 8;
#pragma unroll
        for (int ni = 0; ni < 8; ni++) {
            int col = CN + ni * 8 + qcol;
            if (r0 < N_NODES)
                *(float2*)(g_xt + ((size_t)t * N_NODES + r0) * D_OUT + col) =
                    make_float2(acc[mi][ni][0], acc[mi][ni][1]);
            if (r1 < N_NODES)
                *(float2*)(g_xt + ((size_t)t * N_NODES + r1) * D_OUT + col) =
                    make_float2(acc[mi][ni][2], acc[mi][ni][3]);
        }
    }
}

/* ============================================================================
 * K2: per-(type,node,head) endpoint scores (row stride 20)
 * ==========================================================================*/
__global__ __launch_bounds__(256) void score_kernel(const float* __restrict__ att) {
    __shared__ float att_s[N_CONF * HEADS * 2 * OUT_CH]; /* 1280 floats */
    for (int i = threadIdx.x; i < N_CONF * HEADS * 2 * OUT_CH; i += 256)
        att_s[i] = att[i];
    __syncthreads();

    int id = blockIdx.x * 256 + threadIdx.x;
    if (id >= SEG * HEADS) return;
    int h  = id & 3;
    int nn = id >> 2;   /* = t*N + n */

    const float4* v4 = (const float4*)(g_xt + (size_t)nn * D_OUT + h * 32);
    float si[5] = {0, 0, 0, 0, 0}, sj[5] = {0, 0, 0, 0, 0};
#pragma unroll
    for (int q = 0; q < 8; q++) {
        float4 v = v4[q];
#pragma unroll
        for (int k = 0; k < N_CONF; k++) {
            float4 ai = ((const float4*)att_s)[(k * HEADS + h) * 16 + q];
            float4 aj = ((const float4*)att_s)[(k * HEADS + h) * 16 + 8 + q];
            si[k] += v.x * ai.x + v.y * ai.y + v.z * ai.z + v.w * ai.w;
            sj[k] += v.x * aj.x + v.y * aj.y + v.z * aj.z + v.w * aj.w;
        }
    }
    float* so_i = g_si + (size_t)nn * SROW + h * N_CONF;
    float* so_j = g_sj + (size_t)nn * SROW + h * N_CONF;
#pragma unroll
    for (int k = 0; k < N_CONF; k++) { so_i[k] = si[k]; so_j[k] = sj[k]; }
}

/* ============================================================================
 * CSR build: histogram -> 3-phase scan -> scatter (packed src|t<<16)
 * ==========================================================================*/
__global__ void hist_kernel(const int* __restrict__ ei, const int* __restrict__ et) {
    int e = blockIdx.x * 256 + threadIdx.x;
    if (e >= N_EDGES) return;
    int d = ei[N_EDGES + e];
    int t = et[e];
    atomicAdd(&g_cnt[d * 4 + t], 1);
}

__device__ __forceinline__ int block_scan_1024(int v, int* smem32, int* tot) {
    int lane = threadIdx.x & 31, w = threadIdx.x >> 5;
    int inc = v;
#pragma unroll
    for (int o = 1; o < 32; o <<= 1) {
        int u = __shfl_up_sync(0xffffffffu, inc, o);
        if (lane >= o) inc += u;
    }
    if (lane == 31) smem32[w] = inc;
    __syncthreads();
    if (w == 0) {
        int ws = smem32[lane];
#pragma unroll
        for (int o = 1; o < 32; o <<= 1) {
            int u = __shfl_up_sync(0xffffffffu, ws, o);
            if (lane >= o) ws += u;
        }
        smem32[lane] = ws;
    }
    __syncthreads();
    int base = (w == 0) ? 0 : smem32[w - 1];
    *tot = smem32[31];
    return inc + base;
}

__global__ __launch_bounds__(1024) void scan_phase1() {
    int idx = blockIdx.x * 1024 + threadIdx.x;
    int v = (idx < SEG) ? g_cnt[idx] : 0;
    __shared__ int smem32[32];
    int tot;
    block_scan_1024(v, smem32, &tot);
    if (threadIdx.x == 0) g_bsum[blockIdx.x] = tot;
}

__global__ __launch_bounds__(256) void scan_phase2() {
    __shared__ int smem32[32];
    int v = (threadIdx.x < SCAN_BLOCKS) ? g_bsum[threadIdx.x] : 0;
    int lane = threadIdx.x & 31, w = threadIdx.x >> 5;
    int inc = v;
#pragma unroll
    for (int o = 1; o < 32; o <<= 1) {
        int u = __shfl_up_sync(0xffffffffu, inc, o);
        if (lane >= o) inc += u;
    }
    if (lane == 31) smem32[w] = inc;
    __syncthreads();
    if (w == 0) {
        int ws = (lane < 8) ? smem32[lane] : 0;
#pragma unroll
        for (int o = 1; o < 8; o <<= 1) {
            int u = __shfl_up_sync(0xffffffffu, ws, o);
            if (lane >= o) ws += u;
        }
        if (lane < 8) smem32[lane] = ws;
    }
    __syncthreads();
    int base = (w == 0) ? 0 : smem32[w - 1];
    int excl = inc + base - v;
    if (threadIdx.x < SCAN_BLOCKS) g_bsum[threadIdx.x] = excl;
}

__global__ __launch_bounds__(1024) void scan_phase3() {
    int idx = blockIdx.x * 1024 + threadIdx.x;
    int v = (idx < SEG) ? g_cnt[idx] : 0;
    __shared__ int smem32[32];
    int tot;
    int inc = block_scan_1024(v, smem32, &tot);
    int excl = inc - v + g_bsum[blockIdx.x];
    if (idx < SEG) {
        g_offs[idx]   = excl;
        g_cursor[idx] = excl;
        if (idx == SEG - 1) g_offs[SEG] = excl + v;
    }
}

__global__ void scatter_kernel(const int* __restrict__ ei, const int* __restrict__ et) {
    int e = blockIdx.x * 256 + threadIdx.x;
    if (e >= N_EDGES) return;
    int src = ei[e];
    int d   = ei[N_EDGES + e];
    int t   = et[e];
    int pos = atomicAdd(&g_cursor[d * 4 + t], 1);
    g_rec[pos] = src | (t << 16);
}

/* ============================================================================
 * K4: one warp per dst node (fast path degree<=32; slow path otherwise).
 * ==========================================================================*/
__global__ __launch_bounds__(256) void node_kernel(const float* __restrict__ conf,
                                                   const float* __restrict__ eimp,
                                                   const float* __restrict__ bias,
                                                   float* __restrict__ out) {
    const unsigned FULL = 0xffffffffu;
    __shared__ float w_s[8][32][4];
    __shared__ int   r_s[8][32];
    __shared__ float md[8][32];
    int gw   = (blockIdx.x * blockDim.x + threadIdx.x) >> 5;
    int wib  = threadIdx.x >> 5;
    int lane = threadIdx.x & 31;
    if (gw >= N_NODES) return;
    const int dst = gw;
    const int hl  = lane >> 3;

    float c0 = conf[0], c1 = conf[1], c2 = conf[2], c3 = conf[3], c4 = conf[4];
    float mx = fmaxf(fmaxf(fmaxf(c0, c1), fmaxf(c2, c3)), c4);
    float e0 = __expf(c0 - mx), e1 = __expf(c1 - mx), e2 = __expf(c2 - mx);
    float e3 = __expf(c3 - mx), e4 = __expf(c4 - mx);
    float inv = 1.f / (e0 + e1 + e2 + e3 + e4);
    float pk[5] = {e0 * inv, e1 * inv, e2 * inv, e3 * inv, e4 * inv};
    float eim[4] = {eimp[0], eimp[1], eimp[2], eimp[3]};

    int s0 = g_offs[dst * 4];
    int s1 = g_offs[dst * 4 + 4];
    int total = s1 - s0;

    float4 acc = make_float4(0.f, 0.f, 0.f, 0.f);

    if (total <= 32) {
        bool act = lane < total;
        int pack = act ? g_rec[s0 + lane] : 0;
        int myt  = pack >> 16;
        int src  = pack & 0xFFFF;

        float a0[4];
        {
            const float4* sip = (const float4*)(g_si + ((size_t)myt * N_NODES + dst) * SROW);
            const float4* sjp = (const float4*)(g_sj + ((size_t)myt * N_NODES + src) * SROW);
            float si[20], sj[20];
#pragma unroll
            for (int q = 0; q < 5; q++) {
                float4 u = sip[q];
                si[q * 4 + 0] = u.x; si[q * 4 + 1] = u.y; si[q * 4 + 2] = u.z; si[q * 4 + 3] = u.w;
                float4 v = sjp[q];
                sj[q * 4 + 0] = v.x; sj[q * 4 + 1] = v.y; sj[q * 4 + 2] = v.z; sj[q * 4 + 3] = v.w;
            }
#pragma unroll
            for (int h = 0; h < 4; h++) {
                float ah = 0.f;
#pragma unroll
                for (int k = 0; k < N_CONF; k++) {
                    float v = si[h * 5 + k] + sj[h * 5 + k];
                    v = (v > 0.f) ? v : 0.2f * v;
                    ah += pk[k] * v;
                }
                a0[h] = ah;
            }
        }

        float m[4];
#pragma unroll
        for (int h = 0; h < 4; h++) {
            float v = act ? a0[h] : -1e30f;
#pragma unroll
            for (int o = 16; o; o >>= 1) v = fmaxf(v, __shfl_xor_sync(FULL, v, o));
            m[h] = v;
        }

        float e[4], P[4];
#pragma unroll
        for (int h = 0; h < 4; h++) {
            e[h] = act ? __expf(a0[h] - m[h]) : 0.f;
            P[h] = e[h];
#pragma unroll
            for (int o = 1; o < 32; o <<= 1) {
                float u = __shfl_up_sync(FULL, P[h], o);
                if (lane >= o) P[h] += u;
            }
        }

        unsigned b0m = __ballot_sync(FULL, act && myt == 0);
        unsigned b1m = __ballot_sync(FULL, act && myt == 1);
        unsigned b2m = __ballot_sync(FULL, act && myt == 2);
        unsigned b3m = __ballot_sync(FULL, act && myt == 3);
        unsigned bmy = myt == 0 ? b0m : myt == 1 ? b1m : myt == 2 ? b2m : b3m;
        int hi = (31 - __clz(bmy | 1u)) & 31;
        int lo = __ffs(bmy) - 1;

        float es = sel4(eim, myt);
        float w[4];
#pragma unroll
        for (int h = 0; h < 4; h++) {
            float ph = __shfl_sync(FULL, P[h], hi);
            float pl = __shfl_sync(FULL, P[h], (lo - 1) & 31);
            float dh = ph - (lo > 0 ? pl : 0.f);
            w[h] = act ? e[h] * es / dh : 0.f;
        }

        *(float4*)&w_s[wib][lane][0] = make_float4(w[0], w[1], w[2], w[3]);
        r_s[wib][lane] = myt * N_NODES + src;
        __syncwarp();

#pragma unroll 4
        for (int q = 0; q < total; q++) {
            int   r  = r_s[wib][q];
            float ww = w_s[wib][q][hl];
            float4 xv = ((const float4*)(g_xt + ((size_t)r << 7)))[lane];
            acc.x += ww * xv.x;
            acc.y += ww * xv.y;
            acc.z += ww * xv.z;
            acc.w += ww * xv.w;
        }
    } else {
        bool act = lane < total;
        int pack = act ? g_rec[s0 + lane] : 0;
        int myt  = pack >> 16;
        int src  = pack & 0xFFFF;

        float a0[4];
        {
            const float* sirow = g_si + ((size_t)myt * N_NODES + dst) * SROW;
            const float* sjrow = g_sj + ((size_t)myt * N_NODES + src) * SROW;
#pragma unroll
            for (int h = 0; h < 4; h++) {
                float ah = 0.f;
#pragma unroll
                for (int k = 0; k < N_CONF; k++) {
                    float v = sirow[h * 5 + k] + sjrow[h * 5 + k];
                    v = (v > 0.f) ? v : 0.2f * v;
                    ah += pk[k] * v;
                }
                a0[h] = ah;
            }
        }
#pragma unroll
        for (int tt = 0; tt < 4; tt++)
#pragma unroll
            for (int hh = 0; hh < 4; hh++) {
                float v = (act && myt == tt) ? a0[hh] : -1e30f;
#pragma unroll
                for (int o = 16; o; o >>= 1) v = fmaxf(v, __shfl_xor_sync(FULL, v, o));
                md[wib][tt * 4 + hh] = v;
            }
        __syncwarp();
#pragma unroll 1
        for (int eb = 32; eb < total; eb += 32) {
            bool a2 = eb + lane < total;
            int pk2 = a2 ? g_rec[s0 + eb + lane] : 0;
            int t2 = pk2 >> 16, s2 = pk2 & 0xFFFF;
            const float* sirow = g_si + ((size_t)t2 * N_NODES + dst) * SROW;
            const float* sjrow = g_sj + ((size_t)t2 * N_NODES + s2) * SROW;
            float aa[4];
#pragma unroll
            for (int h = 0; h < 4; h++) {
                float ah = 0.f;
#pragma unroll
                for (int k = 0; k < N_CONF; k++) {
                    float v = sirow[h * 5 + k] + sjrow[h * 5 + k];
                    v = (v > 0.f) ? v : 0.2f * v;
                    ah += pk[k] * v;
                }
                aa[h] = ah;
            }
#pragma unroll
            for (int tt = 0; tt < 4; tt++)
#pragma unroll
                for (int hh = 0; hh < 4; hh++) {
                    float v = (a2 && t2 == tt) ? aa[hh] : -1e30f;
#pragma unroll
                    for (int o = 16; o; o >>= 1) v = fmaxf(v, __shfl_xor_sync(FULL, v, o));
                    if (v > md[wib][tt * 4 + hh]) md[wib][tt * 4 + hh] = v;
                }
            __syncwarp();
        }
#pragma unroll
        for (int tt = 0; tt < 4; tt++)
#pragma unroll
            for (int hh = 0; hh < 4; hh++) {
                float v = (act && myt == tt) ? __expf(a0[hh] - md[wib][tt * 4 + hh]) : 0.f;
#pragma unroll
                for (int o = 16; o; o >>= 1) v += __shfl_xor_sync(FULL, v, o);
                md[wib][16 + tt * 4 + hh] = v;
            }
        __syncwarp();
#pragma unroll 1
        for (int eb = 32; eb < total; eb += 32) {
            bool a2 = eb + lane < total;
            int pk2 = a2 ? g_rec[s0 + eb + lane] : 0;
            int t2 = pk2 >> 16, s2 = pk2 & 0xFFFF;
            const float* sirow = g_si + ((size_t)t2 * N_NODES + dst) * SROW;
            const float* sjrow = g_sj + ((size_t)t2 * N_NODES + s2) * SROW;
            float aa[4];
#pragma unroll
            for (int h = 0; h < 4; h++) {
                float ah = 0.f;
#pragma unroll
                for (int k = 0; k < N_CONF; k++) {
                    float v = sirow[h * 5 + k] + sjrow[h * 5 + k];
                    v = (v > 0.f) ? v : 0.2f * v;
                    ah += pk[k] * v;
                }
                aa[h] = ah;
            }
#pragma unroll
            for (int tt = 0; tt < 4; tt++)
#pragma unroll
                for (int hh = 0; hh < 4; hh++) {
                    float v = (a2 && t2 == tt) ? __expf(aa[hh] - md[wib][tt * 4 + hh]) : 0.f;
#pragma unroll
                    for (int o = 16; o; o >>= 1) v += __shfl_xor_sync(FULL, v, o);
                    md[wib][16 + tt * 4 + hh] += v;
                }
            __syncwarp();
        }
#pragma unroll 1
        for (int q = 0; q < total; q++) {
            int pk2 = g_rec[s0 + q];
            int t = pk2 >> 16, s = pk2 & 0xFFFF;
            const float* sirow = g_si + ((size_t)t * N_NODES + dst) * SROW + hl * 5;
            const float* sjrow = g_sj + ((size_t)t * N_NODES + s) * SROW + hl * 5;
            float aa = 0.f;
#pragma unroll
            for (int k = 0; k < N_CONF; k++) {
                float v = sirow[k] + sjrow[k];
                v = (v > 0.f) ? v : 0.2f * v;
                aa += pk[k] * v;
            }
            float ww = __expf(aa - md[wib][t * 4 + hl]) * sel4(eim, t)
                       / md[wib][16 + t * 4 + hl];
            float4 xv = ((const float4*)(g_xt + (((size_t)t * N_NODES + s) << 7)))[lane];
            acc.x += ww * xv.x;
            acc.y += ww * xv.y;
            acc.z += ww * xv.z;
            acc.w += ww * xv.w;
        }
    }

    float4 self = ((const float4*)(g_xt + ((size_t)dst << 7)))[lane];
    float4 bb   = ((const float4*)bias)[lane];
    float4 o;
    o.x = acc.x + self.x + bb.x;
    o.y = acc.y + self.y + bb.y;
    o.z = acc.z + self.z + bb.z;
    o.w = acc.w + self.w + bb.w;
    ((float4*)(out + (size_t)dst * D_OUT))[lane] = o;
}

/* ============================================================================ */
extern "C" void kernel_launch(void* const* d_in, const int* in_sizes, int n_in,
                              void* d_out, int out_size) {
    const float* x    = (const float*)d_in[0];
    const int*   ei   = (const int*)d_in[1];
    const int*   et   = (const int*)d_in[2];
    const float* W    = (const float*)d_in[3];
    const float* att  = (const float*)d_in[4];
    const float* conf = (const float*)d_in[5];
    const float* eimp = (const float*)d_in[6];
    const float* bias = (const float*)d_in[7];
    float*       out  = (float*)d_out;

    void* cntp = nullptr;
    cudaGetSymbolAddress(&cntp, g_cnt);
    cudaMemsetAsync(cntp, 0, SEG * sizeof(int));

    hist_kernel<<<(N_EDGES + 255) / 256, 256>>>(ei, et);
    scan_phase1<<<SCAN_BLOCKS, 1024>>>();
    scan_phase2<<<1, 256>>>();
    scan_phase3<<<SCAN_BLOCKS, 1024>>>();
    scatter_kernel<<<(N_EDGES + 255) / 256, 256>>>(ei, et);

    split_w_kernel<<<(N_TYPES * IN_CH * D_OUT + 255) / 256, 256>>>(W);

    cudaFuncSetAttribute(gemm_mma_kernel,
                         cudaFuncAttributeMaxDynamicSharedMemorySize, SM_GEMM_TOTAL);
    dim3 gg((N_NODES + 127) / 128, N_TYPES);
    gemm_mma_kernel<<<gg, 256, SM_GEMM_TOTAL>>>(x);

    score_kernel<<<(SEG * HEADS + 255) / 256, 256>>>(att);
    node_kernel<<<(N_NODES * 32 + 255) / 256, 256>>>(conf, eimp, bias, out);
}